// round 5
// baseline (speedup 1.0000x reference)
#include <cuda_runtime.h>

#define BB    16
#define HWSZ  4096
#define DIMC  256
#define NQKV  192
#define NHD   8
#define CRN   64
#define SCALEF 0.17677669529663687f

#define PLANE 364
#define RSTR  36

typedef unsigned long long ull;

__device__ float g_qkv[BB * NQKV * HWSZ];
__device__ float g_y  [BB * CRN  * HWSZ];

__device__ __forceinline__ ull fma2(ull a, ull b, ull c) {
    ull d;
    asm("fma.rn.f32x2 %0, %1, %2, %3;" : "=l"(d) : "l"(a), "l"(b), "l"(c));
    return d;
}
__device__ __forceinline__ ull add2(ull a, ull b) {
    ull d;
    asm("add.rn.f32x2 %0, %1, %2;" : "=l"(d) : "l"(a), "l"(b));
    return d;
}
__device__ __forceinline__ ull mul2(ull a, ull b) {
    ull d;
    asm("mul.rn.f32x2 %0, %1, %2;" : "=l"(d) : "l"(a), "l"(b));
    return d;
}
__device__ __forceinline__ ull pack2(float lo, float hi) {
    ull d;
    asm("mov.b64 %0, {%1, %2};" : "=l"(d)
        : "r"(__float_as_uint(lo)), "r"(__float_as_uint(hi)));
    return d;
}
__device__ __forceinline__ float lo32(ull v) {
    return __uint_as_float((unsigned)(v & 0xffffffffu));
}
__device__ __forceinline__ float hi32(ull v) {
    return __uint_as_float((unsigned)(v >> 32));
}
__device__ __forceinline__ void cp16(void* smem, const void* g) {
    unsigned s = (unsigned)__cvta_generic_to_shared(smem);
    asm volatile("cp.async.cg.shared.global [%0], [%1], 16;" :: "r"(s), "l"(g));
}
__device__ __forceinline__ void cp_commit() {
    asm volatile("cp.async.commit_group;");
}
__device__ __forceinline__ void cp_wait0() {
    asm volatile("cp.async.wait_group 0;");
}

// C(N x 4096) = W(N x K) * X(K x 4096) + bias, per batch (grid.z).
// Block: 128 threads, tile 64n x 128m, thread tile 8n x 8m, BK=16.
// W pre-duplicated as (w,w) f32x2 pairs in smem -> broadcast LDS on compute.
__global__ __launch_bounds__(128) void gemm_kernel(
    const float* __restrict__ Wm,
    const float* __restrict__ Xm,
    const float* __restrict__ bias,
    float* __restrict__ Ym,
    int K, long xStride, long yStride)
{
    const int b  = blockIdx.z;
    const int n0 = blockIdx.y * 64;
    const int m0 = blockIdx.x * 128;
    const float* X = Xm + (long)b * xStride;
    float*       Y = Ym + (long)b * yStride;

    __shared__ float sX[2][16][128];
    __shared__ ull   sW2[2][16][64];

    const int tid = threadIdx.x;
    const int tm4 = (tid & 15) * 4;       // m-group A; group B at +64
    const int tn  = (tid >> 4) * 8;       // 8 n per thread

    const int xr  = tid >> 3;             // 0..15 (k row)
    const int xc  = (tid & 7) * 16;       // col base, 4 cp16s
    const int wn  = tid >> 1;             // 0..63
    const int wk8 = (tid & 1) * 8;        // k half

    ull acc[8][4];
#pragma unroll
    for (int n = 0; n < 8; n++)
#pragma unroll
        for (int j = 0; j < 4; j++) acc[n][j] = 0ULL;

    const int KT = K / 16;

    // prologue: stage tile 0
    {
#pragma unroll
        for (int j = 0; j < 4; j++)
            cp16(&sX[0][xr][xc + 4 * j], &X[(long)xr * HWSZ + m0 + xc + 4 * j]);
        cp_commit();
        float4 wa = *(const float4*)&Wm[(long)(n0 + wn) * K + wk8];
        float4 wb = *(const float4*)&Wm[(long)(n0 + wn) * K + wk8 + 4];
        sW2[0][wk8 + 0][wn] = pack2(wa.x, wa.x);
        sW2[0][wk8 + 1][wn] = pack2(wa.y, wa.y);
        sW2[0][wk8 + 2][wn] = pack2(wa.z, wa.z);
        sW2[0][wk8 + 3][wn] = pack2(wa.w, wa.w);
        sW2[0][wk8 + 4][wn] = pack2(wb.x, wb.x);
        sW2[0][wk8 + 5][wn] = pack2(wb.y, wb.y);
        sW2[0][wk8 + 6][wn] = pack2(wb.z, wb.z);
        sW2[0][wk8 + 7][wn] = pack2(wb.w, wb.w);
        cp_wait0();
    }
    __syncthreads();

    for (int kt = 0; kt < KT; kt++) {
        const int cur = kt & 1;
        const int nxt = cur ^ 1;
        const bool more = (kt + 1 < KT);
        float4 wa, wb;
        if (more) {
            int k0 = (kt + 1) * 16;
#pragma unroll
            for (int j = 0; j < 4; j++)
                cp16(&sX[nxt][xr][xc + 4 * j],
                     &X[(long)(k0 + xr) * HWSZ + m0 + xc + 4 * j]);
            cp_commit();
            wa = *(const float4*)&Wm[(long)(n0 + wn) * K + k0 + wk8];
            wb = *(const float4*)&Wm[(long)(n0 + wn) * K + k0 + wk8 + 4];
        }
#pragma unroll
        for (int k = 0; k < 16; k++) {
            ulonglong2 xa = *(const ulonglong2*)&sX[cur][k][tm4];
            ulonglong2 xb = *(const ulonglong2*)&sX[cur][k][tm4 + 64];
            const ulonglong2* wp = (const ulonglong2*)&sW2[cur][k][tn];
            ulonglong2 w01 = wp[0], w23 = wp[1], w45 = wp[2], w67 = wp[3];
            acc[0][0] = fma2(w01.x, xa.x, acc[0][0]);
            acc[0][1] = fma2(w01.x, xa.y, acc[0][1]);
            acc[0][2] = fma2(w01.x, xb.x, acc[0][2]);
            acc[0][3] = fma2(w01.x, xb.y, acc[0][3]);
            acc[1][0] = fma2(w01.y, xa.x, acc[1][0]);
            acc[1][1] = fma2(w01.y, xa.y, acc[1][1]);
            acc[1][2] = fma2(w01.y, xb.x, acc[1][2]);
            acc[1][3] = fma2(w01.y, xb.y, acc[1][3]);
            acc[2][0] = fma2(w23.x, xa.x, acc[2][0]);
            acc[2][1] = fma2(w23.x, xa.y, acc[2][1]);
            acc[2][2] = fma2(w23.x, xb.x, acc[2][2]);
            acc[2][3] = fma2(w23.x, xb.y, acc[2][3]);
            acc[3][0] = fma2(w23.y, xa.x, acc[3][0]);
            acc[3][1] = fma2(w23.y, xa.y, acc[3][1]);
            acc[3][2] = fma2(w23.y, xb.x, acc[3][2]);
            acc[3][3] = fma2(w23.y, xb.y, acc[3][3]);
            acc[4][0] = fma2(w45.x, xa.x, acc[4][0]);
            acc[4][1] = fma2(w45.x, xa.y, acc[4][1]);
            acc[4][2] = fma2(w45.x, xb.x, acc[4][2]);
            acc[4][3] = fma2(w45.x, xb.y, acc[4][3]);
            acc[5][0] = fma2(w45.y, xa.x, acc[5][0]);
            acc[5][1] = fma2(w45.y, xa.y, acc[5][1]);
            acc[5][2] = fma2(w45.y, xb.x, acc[5][2]);
            acc[5][3] = fma2(w45.y, xb.y, acc[5][3]);
            acc[6][0] = fma2(w67.x, xa.x, acc[6][0]);
            acc[6][1] = fma2(w67.x, xa.y, acc[6][1]);
            acc[6][2] = fma2(w67.x, xb.x, acc[6][2]);
            acc[6][3] = fma2(w67.x, xb.y, acc[6][3]);
            acc[7][0] = fma2(w67.y, xa.x, acc[7][0]);
            acc[7][1] = fma2(w67.y, xa.y, acc[7][1]);
            acc[7][2] = fma2(w67.y, xb.x, acc[7][2]);
            acc[7][3] = fma2(w67.y, xb.y, acc[7][3]);
        }
        if (more) {
            sW2[nxt][wk8 + 0][wn] = pack2(wa.x, wa.x);
            sW2[nxt][wk8 + 1][wn] = pack2(wa.y, wa.y);
            sW2[nxt][wk8 + 2][wn] = pack2(wa.z, wa.z);
            sW2[nxt][wk8 + 3][wn] = pack2(wa.w, wa.w);
            sW2[nxt][wk8 + 4][wn] = pack2(wb.x, wb.x);
            sW2[nxt][wk8 + 5][wn] = pack2(wb.y, wb.y);
            sW2[nxt][wk8 + 6][wn] = pack2(wb.z, wb.z);
            sW2[nxt][wk8 + 7][wn] = pack2(wb.w, wb.w);
            cp_wait0();
        }
        __syncthreads();
    }

#pragma unroll
    for (int n = 0; n < 8; n++) {
        int nn = n0 + tn + n;
        float bs = bias[nn];
        ull bd = pack2(bs, bs);
        ulonglong2 ra, rb;
        ra.x = add2(acc[n][0], bd);
        ra.y = add2(acc[n][1], bd);
        rb.x = add2(acc[n][2], bd);
        rb.y = add2(acc[n][3], bd);
        *(ulonglong2*)&Y[(long)nn * HWSZ + m0 + tm4]      = ra;
        *(ulonglong2*)&Y[(long)nn * HWSZ + m0 + tm4 + 64] = rb;
    }
}

// Fused slide attention: one lane = one channel x 4 consecutive positions
// packed as two f32x2 pairs. Depthwise weights pre-paired in smem.
// Block = 256 threads; covers (b, head, 8 rows x 32 cols).
__global__ __launch_bounds__(256) void attn_kernel(
    const float* __restrict__ qkv,
    const float* __restrict__ w1,
    const float* __restrict__ dcb,
    const float* __restrict__ dc1b,
    const float* __restrict__ rpb,
    float* __restrict__ y)
{
    const int b   = blockIdx.z;
    const int hd  = blockIdx.y;
    const int rt  = blockIdx.x >> 1;
    const int ct  = blockIdx.x & 1;
    const int h0  = rt * 8;
    const int gw0 = ct * 32;

    __shared__ float sk[8 * PLANE];
    __shared__ float sv[8 * PLANE];
    __shared__ ull   sw2[8][81];
    __shared__ ull   sbk2[8][9];
    __shared__ ull   sbv2[8][9];

    const int tid  = threadIdx.x;
    const int lane = tid & 31;
    const int warp = tid >> 5;
    const int c    = lane & 7;
    const int g    = lane >> 3;

    const float* base = qkv + ((long)b * NQKV + hd * 24) * HWSZ;

    for (int i = tid; i < 648; i += 256) {
        int cc = i / 81, idx = i - cc * 81;
        float w = w1[cc * 81 + idx];
        sw2[cc][idx] = pack2(w, w);
    }
    for (int i = tid; i < 72; i += 256) {
        int cc = i / 9, t = i - cc * 9;
        float bb = dcb[i] + dc1b[i];
        sbv2[cc][t] = pack2(bb, bb);
        float bk = bb + rpb[hd * 9 + t];
        sbk2[cc][t] = pack2(bk, bk);
    }
    for (int i = tid; i < 8 * 340; i += 256) {
        int cc = i / 340, rem = i - cc * 340;
        int yy = rem / 34, xx = rem - yy * 34;
        int gh = h0 + yy - 1;
        int gx = gw0 + xx - 1;
        float kk = 0.f, vv = 0.f;
        if (gh >= 0 && gh < 64 && gx >= 0 && gx < 64) {
            long off = (long)(8 + cc) * HWSZ + gh * 64 + gx;
            kk = base[off];
            vv = base[off + 8 * HWSZ];
        }
        sk[cc * PLANE + yy * RSTR + xx] = kk;
        sv[cc * PLANE + yy * RSTR + xx] = vv;
    }
    __syncthreads();

    const ull* wrow = sw2[c];

#pragma unroll 1
    for (int step = 0; step < 2; step++) {
        const int task = step * 8 + warp;    // 0..15
        const int row  = task >> 1;
        const int half = task & 1;
        const int w0   = half * 16 + g * 4;
        const int hw   = (h0 + row) * 64 + gw0 + w0;

        float4 qv = *(const float4*)&base[(long)c * HWSZ + hw];
        ull q0 = pack2(qv.x * SCALEF, qv.y * SCALEF);
        ull q1 = pack2(qv.z * SCALEF, qv.w * SCALEF);

        ull nk[3][5];
        {
            const float* p = &sk[c * PLANE + row * RSTR + w0];
#pragma unroll
            for (int ty = 0; ty < 3; ty++) {
                float4 a  = *(const float4*)(p + ty * RSTR);
                float2 a2 = *(const float2*)(p + ty * RSTR + 4);
                nk[ty][0] = pack2(a.x, a.y);
                nk[ty][1] = pack2(a.y, a.z);
                nk[ty][2] = pack2(a.z, a.w);
                nk[ty][3] = pack2(a.w, a2.x);
                nk[ty][4] = pack2(a2.x, a2.y);
            }
        }

        ull lg0[9], lg1[9];
#pragma unroll
        for (int t = 0; t < 9; t++) {
            const int ty = t / 3, tx = t - ty * 3;
            ull bk  = sbk2[c][t];
            ull kv0 = add2(nk[ty][tx],     bk);
            ull kv1 = add2(nk[ty][tx + 2], bk);
#pragma unroll
            for (int i = 0; i < 9; i++) {
                const int iy = i / 3, ix = i - iy * 3;
                ull wp = wrow[t * 9 + i];
                kv0 = fma2(wp, nk[iy][ix],     kv0);
                kv1 = fma2(wp, nk[iy][ix + 2], kv1);
            }
            lg0[t] = mul2(q0, kv0);
            lg1[t] = mul2(q1, kv1);
        }

        float lf[4][9];
#pragma unroll
        for (int t = 0; t < 9; t++) {
            lf[0][t] = lo32(lg0[t]); lf[1][t] = hi32(lg0[t]);
            lf[2][t] = lo32(lg1[t]); lf[3][t] = hi32(lg1[t]);
        }
#pragma unroll
        for (int off = 4; off >= 1; off >>= 1)
#pragma unroll
            for (int p = 0; p < 4; p++)
#pragma unroll
                for (int t = 0; t < 9; t++)
                    lf[p][t] += __shfl_xor_sync(0xffffffffu, lf[p][t], off);

#pragma unroll
        for (int p = 0; p < 4; p++) {
            float m = lf[p][0];
#pragma unroll
            for (int t = 1; t < 9; t++) m = fmaxf(m, lf[p][t]);
            float s = 0.f;
#pragma unroll
            for (int t = 0; t < 9; t++) { lf[p][t] = __expf(lf[p][t] - m); s += lf[p][t]; }
            float inv = 1.f / s;
#pragma unroll
            for (int t = 0; t < 9; t++) lf[p][t] *= inv;
        }

        ull nv[3][5];
        {
            const float* p = &sv[c * PLANE + row * RSTR + w0];
#pragma unroll
            for (int ty = 0; ty < 3; ty++) {
                float4 a  = *(const float4*)(p + ty * RSTR);
                float2 a2 = *(const float2*)(p + ty * RSTR + 4);
                nv[ty][0] = pack2(a.x, a.y);
                nv[ty][1] = pack2(a.y, a.z);
                nv[ty][2] = pack2(a.z, a.w);
                nv[ty][3] = pack2(a.w, a2.x);
                nv[ty][4] = pack2(a2.x, a2.y);
            }
        }
        float o0 = 0.f, o1 = 0.f, o2 = 0.f, o3 = 0.f;
#pragma unroll
        for (int t = 0; t < 9; t++) {
            const int ty = t / 3, tx = t - ty * 3;
            ull bv  = sbv2[c][t];
            ull vv0 = add2(nv[ty][tx],     bv);
            ull vv1 = add2(nv[ty][tx + 2], bv);
#pragma unroll
            for (int i = 0; i < 9; i++) {
                const int iy = i / 3, ix = i - iy * 3;
                ull wp = wrow[t * 9 + i];
                vv0 = fma2(wp, nv[iy][ix],     vv0);
                vv1 = fma2(wp, nv[iy][ix + 2], vv1);
            }
            o0 += lf[0][t] * lo32(vv0);
            o1 += lf[1][t] * hi32(vv0);
            o2 += lf[2][t] * lo32(vv1);
            o3 += lf[3][t] * hi32(vv1);
        }
        *(float4*)&y[((long)b * CRN + hd * 8 + c) * HWSZ + hw] =
            make_float4(o0, o1, o2, o3);
    }
}

extern "C" void kernel_launch(void* const* d_in, const int* in_sizes, int n_in,
                              void* d_out, int out_size) {
    const float* x      = (const float*)d_in[0];
    const float* qkv_w  = (const float*)d_in[5];
    const float* qkv_b  = (const float*)d_in[6];
    const float* dcb    = (const float*)d_in[7];
    const float* w1     = (const float*)d_in[8];
    const float* dc1b   = (const float*)d_in[9];
    const float* rpb    = (const float*)d_in[10];
    const float* proj_w = (const float*)d_in[11];
    const float* proj_b = (const float*)d_in[12];
    float* out = (float*)d_out;

    float *qkv = nullptr, *yb = nullptr;
    cudaGetSymbolAddress((void**)&qkv, g_qkv);
    cudaGetSymbolAddress((void**)&yb, g_y);

    gemm_kernel<<<dim3(HWSZ / 128, NQKV / 64, BB), 128>>>(
        qkv_w, x, qkv_b, qkv, DIMC, (long)DIMC * HWSZ, (long)NQKV * HWSZ);

    attn_kernel<<<dim3(16, NHD, BB), 256>>>(qkv, w1, dcb, dc1b, rpb, yb);

    gemm_kernel<<<dim3(HWSZ / 128, DIMC / 64, BB), 128>>>(
        proj_w, yb, proj_b, out, CRN, (long)CRN * HWSZ, (long)DIMC * HWSZ);
}

// round 7
// speedup vs baseline: 1.4835x; 1.4835x over previous
#include <cuda_runtime.h>
#include <cuda_bf16.h>
#include <cstdint>

#define BB    16
#define HWSZ  4096
#define DIMC  256
#define NQKV  192
#define NHD   8
#define CRN   64
#define SCALEF 0.17677669529663687f
#define PLANE 364
#define RSTR  36

typedef unsigned long long ull;
typedef unsigned int u32;

// ---------------- device scratch (allocation-free rule) ----------------
__device__ float g_qkv[BB * NQKV * HWSZ];            // (B,192,4096) fp32
__device__ float g_y  [BB * CRN  * HWSZ];            // (B,64,4096)  fp32
__device__ __nv_bfloat16 g_xt_hi[BB * HWSZ * DIMC];  // (B,4096,256)
__device__ __nv_bfloat16 g_xt_lo[BB * HWSZ * DIMC];
__device__ __nv_bfloat16 g_yt_hi[BB * HWSZ * CRN];   // (B,4096,64)
__device__ __nv_bfloat16 g_yt_lo[BB * HWSZ * CRN];
__device__ __nv_bfloat16 g_wq_hi[NQKV * DIMC];
__device__ __nv_bfloat16 g_wq_lo[NQKV * DIMC];
__device__ __nv_bfloat16 g_wp_hi[DIMC * CRN];
__device__ __nv_bfloat16 g_wp_lo[DIMC * CRN];

// ---------------- PTX helpers ----------------
__device__ __forceinline__ ull fma2(ull a, ull b, ull c) {
    ull d; asm("fma.rn.f32x2 %0, %1, %2, %3;" : "=l"(d) : "l"(a), "l"(b), "l"(c)); return d;
}
__device__ __forceinline__ ull add2(ull a, ull b) {
    ull d; asm("add.rn.f32x2 %0, %1, %2;" : "=l"(d) : "l"(a), "l"(b)); return d;
}
__device__ __forceinline__ ull mul2(ull a, ull b) {
    ull d; asm("mul.rn.f32x2 %0, %1, %2;" : "=l"(d) : "l"(a), "l"(b)); return d;
}
__device__ __forceinline__ ull pack2(float lo, float hi) {
    ull d; asm("mov.b64 %0, {%1, %2};" : "=l"(d)
        : "r"(__float_as_uint(lo)), "r"(__float_as_uint(hi))); return d;
}
__device__ __forceinline__ float lo32(ull v) { return __uint_as_float((unsigned)(v & 0xffffffffu)); }
__device__ __forceinline__ float hi32(ull v) { return __uint_as_float((unsigned)(v >> 32)); }

__device__ __forceinline__ void cp16(void* smem, const void* g) {
    unsigned s = (unsigned)__cvta_generic_to_shared(smem);
    asm volatile("cp.async.cg.shared.global [%0], [%1], 16;" :: "r"(s), "l"(g));
}
__device__ __forceinline__ void cp_commit() { asm volatile("cp.async.commit_group;"); }
__device__ __forceinline__ void cp_wait1()  { asm volatile("cp.async.wait_group 1;"); }
__device__ __forceinline__ void cp_wait0()  { asm volatile("cp.async.wait_group 0;"); }

__device__ __forceinline__ u32 smem_u32(const void* p) {
    return (u32)__cvta_generic_to_shared(p);
}
__device__ __forceinline__ void ldsm4(u32* r, u32 addr) {
    asm volatile("ldmatrix.sync.aligned.m8n8.x4.shared.b16 {%0,%1,%2,%3}, [%4];"
        : "=r"(r[0]), "=r"(r[1]), "=r"(r[2]), "=r"(r[3]) : "r"(addr));
}
__device__ __forceinline__ void mma16816(float* c, const u32* a, const u32* b) {
    asm volatile(
        "mma.sync.aligned.m16n8k16.row.col.f32.bf16.bf16.f32 "
        "{%0,%1,%2,%3}, {%4,%5,%6,%7}, {%8,%9}, {%0,%1,%2,%3};"
        : "+f"(c[0]), "+f"(c[1]), "+f"(c[2]), "+f"(c[3])
        : "r"(a[0]), "r"(a[1]), "r"(a[2]), "r"(a[3]), "r"(b[0]), "r"(b[1]));
}

// ---------------- weight bf16 split ----------------
__global__ void convert_w_kernel(const float* __restrict__ qkv_w,
                                 const float* __restrict__ proj_w) {
    int i = blockIdx.x * 256 + threadIdx.x;
    if (i < NQKV * DIMC) {
        float v = qkv_w[i];
        __nv_bfloat16 h = __float2bfloat16(v);
        g_wq_hi[i] = h;
        g_wq_lo[i] = __float2bfloat16(v - __bfloat162float(h));
    }
    if (i < DIMC * CRN) {
        float v = proj_w[i];
        __nv_bfloat16 h = __float2bfloat16(v);
        g_wp_hi[i] = h;
        g_wp_lo[i] = __float2bfloat16(v - __bfloat162float(h));
    }
}

// ---------------- transpose + bf16 split: src [b][C][4096] -> dT [b][4096][C] ----------------
__global__ void tconv_kernel(const float* __restrict__ src,
                             __nv_bfloat16* __restrict__ dhi,
                             __nv_bfloat16* __restrict__ dlo, int C) {
    __shared__ float t[32][33];
    const int b  = blockIdx.z;
    const int m0 = blockIdx.x * 32;
    const int c0 = blockIdx.y * 32;
    const int tx = threadIdx.x, ty = threadIdx.y;   // 32 x 8
    const float* s = src + ((long)b * C + c0) * HWSZ + m0;
#pragma unroll
    for (int j = 0; j < 32; j += 8)
        t[ty + j][tx] = s[(long)(ty + j) * HWSZ + tx];
    __syncthreads();
    __nv_bfloat16* ph = dhi + ((long)b * HWSZ + m0) * C + c0;
    __nv_bfloat16* pl = dlo + ((long)b * HWSZ + m0) * C + c0;
#pragma unroll
    for (int j = 0; j < 32; j += 8) {
        float v = t[tx][ty + j];
        __nv_bfloat16 h = __float2bfloat16(v);
        ph[(long)(ty + j) * C + tx] = h;
        pl[(long)(ty + j) * C + tx] = __float2bfloat16(v - __bfloat162float(h));
    }
}

// ---------------- bf16-split mma.sync GEMM ----------------
// out[b][n][m] = sum_k W[n][k] * aT[b][m][k] + bias[n]
// CTA tile 128m x 64n, 8 warps (4m x 2n), warp tile 32m x 32n, BK=32.
// Dynamic smem: 2 stages x (A_hi 10240 | A_lo 10240 | B_hi 5120 | B_lo 5120) = 61440 B.
#define STG   30720
#define AROWB 80     // A/B smem row stride bytes (40 bf16)

__global__ __launch_bounds__(256) void gemm_mma_kernel(
    const __nv_bfloat16* __restrict__ aT_hi,
    const __nv_bfloat16* __restrict__ aT_lo,
    const __nv_bfloat16* __restrict__ w_hi,
    const __nv_bfloat16* __restrict__ w_lo,
    const float* __restrict__ bias,
    float* __restrict__ out, int N, int K)
{
    extern __shared__ char sm[];
    const int tid  = threadIdx.x;
    const int lane = tid & 31;
    const int warp = tid >> 5;
    const int wm   = warp & 3;   // m warp: 0..3
    const int wn   = warp >> 2;  // n warp: 0..1
    const int b    = blockIdx.z;
    const int m0   = blockIdx.x * 128;
    const int n0   = blockIdx.y * 64;

    const long arow = (long)b * HWSZ + m0;

    // per-lane ldmatrix sub-addresses
    const int a_row  = lane & 15;
    const int a_colB = (lane >> 4) * 16;          // bytes (8 bf16)
    const int b_row  = (lane & 7) + ((lane >> 4) & 1) * 8;
    const int b_colB = ((lane >> 3) & 1) * 16;    // bytes

    const int aoff = (wm * 32 + a_row) * AROWB + a_colB;
    const int boff = (wn * 32 + b_row) * AROWB + b_colB;

    float acc[2][4][4];
#pragma unroll
    for (int mt = 0; mt < 2; mt++)
#pragma unroll
        for (int ni = 0; ni < 4; ni++)
#pragma unroll
            for (int r = 0; r < 4; r++) acc[mt][ni][r] = 0.f;

    const int KT = K >> 5;

    // stage loader
    auto load_stage = [&](int s, int k0) {
        char* Ah = sm + s * STG;
        char* Al = Ah + 10240;
        char* Bh = Ah + 20480;
        char* Bl = Ah + 25600;
        // A: 128 rows x 64B (hi & lo)
        for (int u = tid; u < 512; u += 256) {
            int r = u >> 2, j = u & 3;
            long go = (arow + r) * K + k0 + j * 8;
            cp16(Ah + r * AROWB + j * 16, aT_hi + go);
            cp16(Al + r * AROWB + j * 16, aT_lo + go);
        }
        // B: 64 rows x 64B (hi & lo)
        for (int u = tid; u < 256; u += 256) {
            int r = u >> 2, j = u & 3;
            long go = (long)(n0 + r) * K + k0 + j * 8;
            cp16(Bh + r * AROWB + j * 16, w_hi + go);
            cp16(Bl + r * AROWB + j * 16, w_lo + go);
        }
        cp_commit();
    };

    load_stage(0, 0);

    for (int kt = 0; kt < KT; kt++) {
        const int cur = kt & 1;
        const bool more = (kt + 1 < KT);
        if (more) load_stage(cur ^ 1, (kt + 1) * 32);
        if (more) cp_wait1(); else cp_wait0();
        __syncthreads();

        const char* sb = sm + cur * STG;
        const u32 aH = smem_u32(sb) + aoff;
        const u32 aL = aH + 10240;
        const u32 bH = smem_u32(sb) + 20480 + boff;
        const u32 bL = bH + 5120;

#pragma unroll
        for (int kk = 0; kk < 2; kk++) {
            u32 ah[2][4], al[2][4], bh[2][4], bl[2][4];
#pragma unroll
            for (int mt = 0; mt < 2; mt++) {
                ldsm4(ah[mt], aH + mt * 16 * AROWB + kk * 32);
                ldsm4(al[mt], aL + mt * 16 * AROWB + kk * 32);
            }
#pragma unroll
            for (int bt = 0; bt < 2; bt++) {
                ldsm4(bh[bt], bH + bt * 16 * AROWB + kk * 32);
                ldsm4(bl[bt], bL + bt * 16 * AROWB + kk * 32);
            }
#pragma unroll
            for (int mt = 0; mt < 2; mt++)
#pragma unroll
                for (int ni = 0; ni < 4; ni++) {
                    const int bt = ni >> 1, h = (ni & 1) * 2;
                    mma16816(acc[mt][ni], ah[mt], &bh[bt][h]);
                    mma16816(acc[mt][ni], ah[mt], &bl[bt][h]);
                    mma16816(acc[mt][ni], al[mt], &bh[bt][h]);
                }
        }
        __syncthreads();
    }

    // epilogue: stage C through smem [m][66] for coalesced n-major writes
    float* Cs = (float*)sm;
#pragma unroll
    for (int mt = 0; mt < 2; mt++)
#pragma unroll
        for (int ni = 0; ni < 4; ni++) {
            int mm = wm * 32 + mt * 16 + (lane >> 2);
            int nn = wn * 32 + ni * 8 + (lane & 3) * 2;
            *(float2*)&Cs[mm * 66 + nn]       = make_float2(acc[mt][ni][0], acc[mt][ni][1]);
            *(float2*)&Cs[(mm + 8) * 66 + nn] = make_float2(acc[mt][ni][2], acc[mt][ni][3]);
        }
    __syncthreads();
    for (int u = tid; u < 64 * 128; u += 256) {
        int n = u >> 7, m = u & 127;
        out[((long)b * N + n0 + n) * HWSZ + m0 + m] = Cs[m * 66 + n] + __ldg(&bias[n0 + n]);
    }
}

// ---------------- fused slide attention (proven R3 version) ----------------
__global__ __launch_bounds__(128) void attn_kernel(
    const float* __restrict__ qkv,
    const float* __restrict__ w1,
    const float* __restrict__ dcb,
    const float* __restrict__ dc1b,
    const float* __restrict__ rpb,
    float* __restrict__ y)
{
    const int b   = blockIdx.z;
    const int hd  = blockIdx.y;
    const int rt  = blockIdx.x >> 1;
    const int ct  = blockIdx.x & 1;
    const int h0  = rt * 8;
    const int gw0 = ct * 32;

    __shared__ float sk[8 * PLANE];
    __shared__ float sv[8 * PLANE];
    __shared__ ull   sw2[8][81];
    __shared__ ull   sbk2[8][9];
    __shared__ ull   sbv2[8][9];

    const int tid  = threadIdx.x;
    const int lane = tid & 31;
    const int warp = tid >> 5;
    const int c    = lane & 7;
    const int g    = lane >> 3;

    const float* base = qkv + ((long)b * NQKV + hd * 24) * HWSZ;

    for (int i = tid; i < 648; i += 128) {
        int cc = i / 81, idx = i - cc * 81;
        float w = w1[cc * 81 + idx];
        sw2[cc][idx] = pack2(w, w);
    }
    for (int i = tid; i < 72; i += 128) {
        int cc = i / 9, t = i - cc * 9;
        float bb = dcb[i] + dc1b[i];
        sbv2[cc][t] = pack2(bb, bb);
        float bk = bb + rpb[hd * 9 + t];
        sbk2[cc][t] = pack2(bk, bk);
    }
    for (int i = tid; i < 8 * 340; i += 128) {
        int cc = i / 340, rem = i - cc * 340;
        int yy = rem / 34, xx = rem - yy * 34;
        int gh = h0 + yy - 1;
        int gx = gw0 + xx - 1;
        float kk = 0.f, vv = 0.f;
        if (gh >= 0 && gh < 64 && gx >= 0 && gx < 64) {
            long off = (long)(8 + cc) * HWSZ + gh * 64 + gx;
            kk = base[off];
            vv = base[off + 8 * HWSZ];
        }
        sk[cc * PLANE + yy * RSTR + xx] = kk;
        sv[cc * PLANE + yy * RSTR + xx] = vv;
    }
    __syncthreads();

    const ull* wrow = sw2[c];

#pragma unroll 1
    for (int step = 0; step < 4; step++) {
        const int task = step * 4 + warp;
        const int row  = task >> 1;
        const int half = task & 1;
        const int w0   = half * 16 + g * 4;
        const int hw   = (h0 + row) * 64 + gw0 + w0;

        float4 qv = *(const float4*)&base[(long)c * HWSZ + hw];
        ull q0 = pack2(qv.x * SCALEF, qv.y * SCALEF);
        ull q1 = pack2(qv.z * SCALEF, qv.w * SCALEF);

        ull nk[3][5];
        {
            const float* p = &sk[c * PLANE + row * RSTR + w0];
#pragma unroll
            for (int ty = 0; ty < 3; ty++) {
                float4 a  = *(const float4*)(p + ty * RSTR);
                float2 a2 = *(const float2*)(p + ty * RSTR + 4);
                nk[ty][0] = pack2(a.x, a.y);
                nk[ty][1] = pack2(a.y, a.z);
                nk[ty][2] = pack2(a.z, a.w);
                nk[ty][3] = pack2(a.w, a2.x);
                nk[ty][4] = pack2(a2.x, a2.y);
            }
        }

        ull lg0[9], lg1[9];
#pragma unroll
        for (int t = 0; t < 9; t++) {
            const int ty = t / 3, tx = t - ty * 3;
            ull bk  = sbk2[c][t];
            ull kv0 = add2(nk[ty][tx],     bk);
            ull kv1 = add2(nk[ty][tx + 2], bk);
#pragma unroll
            for (int i = 0; i < 9; i++) {
                const int iy = i / 3, ix = i - iy * 3;
                ull wp = wrow[t * 9 + i];
                kv0 = fma2(wp, nk[iy][ix],     kv0);
                kv1 = fma2(wp, nk[iy][ix + 2], kv1);
            }
            lg0[t] = mul2(q0, kv0);
            lg1[t] = mul2(q1, kv1);
        }

        float lf[4][9];
#pragma unroll
        for (int t = 0; t < 9; t++) {
            lf[0][t] = lo32(lg0[t]); lf[1][t] = hi32(lg0[t]);
            lf[2][t] = lo32(lg1[t]); lf[3][t] = hi32(lg1[t]);
        }
#pragma unroll
        for (int off = 4; off >= 1; off >>= 1)
#pragma unroll
            for (int p = 0; p < 4; p++)
#pragma unroll
                for (int t = 0; t < 9; t++)
                    lf[p][t] += __shfl_xor_sync(0xffffffffu, lf[p][t], off);

#pragma unroll
        for (int p = 0; p < 4; p++) {
            float m = lf[p][0];
#pragma unroll
            for (int t = 1; t < 9; t++) m = fmaxf(m, lf[p][t]);
            float s = 0.f;
#pragma unroll
            for (int t = 0; t < 9; t++) { lf[p][t] = __expf(lf[p][t] - m); s += lf[p][t]; }
            float inv = 1.f / s;
#pragma unroll
            for (int t = 0; t < 9; t++) lf[p][t] *= inv;
        }

        ull nv[3][5];
        {
            const float* p = &sv[c * PLANE + row * RSTR + w0];
#pragma unroll
            for (int ty = 0; ty < 3; ty++) {
                float4 a  = *(const float4*)(p + ty * RSTR);
                float2 a2 = *(const float2*)(p + ty * RSTR + 4);
                nv[ty][0] = pack2(a.x, a.y);
                nv[ty][1] = pack2(a.y, a.z);
                nv[ty][2] = pack2(a.z, a.w);
                nv[ty][3] = pack2(a.w, a2.x);
                nv[ty][4] = pack2(a2.x, a2.y);
            }
        }
        float o0 = 0.f, o1 = 0.f, o2 = 0.f, o3 = 0.f;
#pragma unroll
        for (int t = 0; t < 9; t++) {
            const int ty = t / 3, tx = t - ty * 3;
            ull bv  = sbv2[c][t];
            ull vv0 = add2(nv[ty][tx],     bv);
            ull vv1 = add2(nv[ty][tx + 2], bv);
#pragma unroll
            for (int i = 0; i < 9; i++) {
                const int iy = i / 3, ix = i - iy * 3;
                ull wp = wrow[t * 9 + i];
                vv0 = fma2(wp, nv[iy][ix],     vv0);
                vv1 = fma2(wp, nv[iy][ix + 2], vv1);
            }
            o0 += lf[0][t] * lo32(vv0);
            o1 += lf[1][t] * hi32(vv0);
            o2 += lf[2][t] * lo32(vv1);
            o3 += lf[3][t] * hi32(vv1);
        }
        *(float4*)&y[((long)b * CRN + hd * 8 + c) * HWSZ + hw] =
            make_float4(o0, o1, o2, o3);
    }
}

// ---------------- launch ----------------
extern "C" void kernel_launch(void* const* d_in, const int* in_sizes, int n_in,
                              void* d_out, int out_size) {
    const float* x      = (const float*)d_in[0];
    const float* qkv_w  = (const float*)d_in[5];
    const float* qkv_b  = (const float*)d_in[6];
    const float* dcb    = (const float*)d_in[7];
    const float* w1     = (const float*)d_in[8];
    const float* dc1b   = (const float*)d_in[9];
    const float* rpb    = (const float*)d_in[10];
    const float* proj_w = (const float*)d_in[11];
    const float* proj_b = (const float*)d_in[12];
    float* out = (float*)d_out;

    float *qkv = nullptr, *yb = nullptr;
    cudaGetSymbolAddress((void**)&qkv, g_qkv);
    cudaGetSymbolAddress((void**)&yb, g_y);
    __nv_bfloat16 *xt_hi, *xt_lo, *yt_hi, *yt_lo, *wq_hi, *wq_lo, *wp_hi, *wp_lo;
    cudaGetSymbolAddress((void**)&xt_hi, g_xt_hi);
    cudaGetSymbolAddress((void**)&xt_lo, g_xt_lo);
    cudaGetSymbolAddress((void**)&yt_hi, g_yt_hi);
    cudaGetSymbolAddress((void**)&yt_lo, g_yt_lo);
    cudaGetSymbolAddress((void**)&wq_hi, g_wq_hi);
    cudaGetSymbolAddress((void**)&wq_lo, g_wq_lo);
    cudaGetSymbolAddress((void**)&wp_hi, g_wp_hi);
    cudaGetSymbolAddress((void**)&wp_lo, g_wp_lo);

    cudaFuncSetAttribute(gemm_mma_kernel,
                         cudaFuncAttributeMaxDynamicSharedMemorySize, 61440);

    // weight split + x transpose/split
    convert_w_kernel<<<192, 256>>>(qkv_w, proj_w);
    tconv_kernel<<<dim3(128, 8, BB), dim3(32, 8)>>>(x, xt_hi, xt_lo, DIMC);

    // qkv = W(192x256) . xT + b   (mma.sync bf16 3-split)
    gemm_mma_kernel<<<dim3(32, 3, BB), 256, 61440>>>(
        xt_hi, xt_lo, wq_hi, wq_lo, qkv_b, qkv, NQKV, DIMC);

    // fused slide attention
    attn_kernel<<<dim3(16, NHD, BB), 128>>>(qkv, w1, dcb, dc1b, rpb, yb);

    // y transpose/split, then proj = W(256x64) . yT + b
    tconv_kernel<<<dim3(128, 2, BB), dim3(32, 8)>>>(yb, yt_hi, yt_lo, CRN);
    gemm_mma_kernel<<<dim3(32, 4, BB), 256, 61440>>>(
        yt_hi, yt_lo, wp_hi, wp_lo, proj_b, out, DIMC, CRN);
}